// round 12
// baseline (speedup 1.0000x reference)
#include <cuda_runtime.h>
#include <cuda_fp16.h>
#include <math.h>

#define N_NODES 10000
#define N_EDGES 640000
#define IN_C    128
#define HID_C   256
#define OUT_C   128
#define GR_TILE 80
#define GR_BLOCKS ((N_NODES + GR_TILE - 1) / GR_TILE)   // 125

// ------------------------- scratch (device globals) -------------------------
// INVARIANT: g_deg and g_c are all-zero at entry of every kernel_launch call.
__device__ int     g_deg[N_NODES];
__device__ float   g_c[N_NODES];           // column sums of normalized adjacency (edge part)
__device__ int     g_off[N_NODES + 1];
__device__ int     g_cursor[N_NODES];
__device__ int     g_csr[N_EDGES];
__device__ float   g_dinv[N_NODES];
__device__ uint4   g_xh[N_NODES * IN_C / 8];  // dinv-scaled x in fp16, row = 16 uint4
__device__ float   g_y[N_NODES * IN_C];       // (A_hat X)
__device__ float   g_w[HID_C];                // W2 @ fc_w
__device__ double  g_part[GR_BLOCKS];         // per-block partial sums

// ------------------------------- kernels ------------------------------------
__global__ void k_count(const int* __restrict__ ei) {
    int e = blockIdx.x * blockDim.x + threadIdx.x;
    if (e < N_EDGES) {
        int dst = ei[N_EDGES + e];
        if ((unsigned)dst < N_NODES) atomicAdd(&g_deg[dst], 1);
    }
}

// single-block scan, all global traffic coalesced via smem staging
__global__ void __launch_bounds__(1024) k_scan_dinv() {
    __shared__ int sbuf[10240];      // 40 KB staging
    __shared__ int warp_sums[32];
    int t = threadIdx.x;
    int lane = t & 31, wid = t >> 5;

    for (int i = t; i < 10240; i += 1024) sbuf[i] = (i < N_NODES) ? g_deg[i] : 0;
    __syncthreads();

    int base = t * 10;
    int vals[10], tot = 0;
    #pragma unroll
    for (int i = 0; i < 10; i++) { vals[i] = sbuf[base + i]; tot += vals[i]; }

    int incl = tot;
    #pragma unroll
    for (int of = 1; of < 32; of <<= 1) {
        int n = __shfl_up_sync(0xffffffffu, incl, of);
        if (lane >= of) incl += n;
    }
    if (lane == 31) warp_sums[wid] = incl;
    __syncthreads();
    if (wid == 0) {
        int s = warp_sums[lane];
        #pragma unroll
        for (int of = 1; of < 32; of <<= 1) {
            int n = __shfl_up_sync(0xffffffffu, s, of);
            if (lane >= of) s += n;
        }
        warp_sums[lane] = s;
    }
    __syncthreads();
    int excl = ((wid > 0) ? warp_sums[wid - 1] : 0) + incl - tot;

    int run = excl;
    int offv[10];
    #pragma unroll
    for (int i = 0; i < 10; i++) { sbuf[base + i] = run; run += vals[i]; offv[i] = run; }
    __syncthreads();
    for (int i = t; i < N_NODES; i += 1024) g_cursor[i] = sbuf[i];
    __syncthreads();

    #pragma unroll
    for (int i = 0; i < 10; i++) sbuf[base + i] = offv[i];
    __syncthreads();
    if (t == 0) g_off[0] = 0;
    for (int i = t; i < N_NODES; i += 1024) g_off[i + 1] = sbuf[i];
    __syncthreads();

    float* sf = (float*)sbuf;
    #pragma unroll
    for (int i = 0; i < 10; i++) sf[base + i] = rsqrtf((float)(vals[i] + 1)); // +1 self loop
    __syncthreads();
    for (int i = t; i < N_NODES; i += 1024) g_dinv[i] = sf[i];
}

// CSR fill + column sums + convert x -> dinv-scaled fp16 (N_EDGES == N_NODES*IN_C/2)
__global__ void k_fill_convert(const int* __restrict__ ei, const float* __restrict__ x) {
    int e = blockIdx.x * blockDim.x + threadIdx.x;
    if (e < N_EDGES) {
        int src = ei[e];
        int dst = ei[N_EDGES + e];
        if ((unsigned)src < N_NODES && (unsigned)dst < N_NODES) {
            int pos = atomicAdd(&g_cursor[dst], 1);
            g_csr[pos] = src;
            atomicAdd(&g_c[src], g_dinv[src] * g_dinv[dst]);
        }
        // convert one float2 of x, scaled by its row's dinv
        float2 v = ((const float2*)x)[e];
        int row = e >> 6;                       // 64 float2 per row
        float di = g_dinv[row];
        ((__half2*)g_xh)[e] = __floats2half2_rn(di * v.x, di * v.y);
    }
}

// w = W2 @ fc_w  (W2: [256,128] row-major, fc_w: [128])
__global__ void k_wvec(const float* __restrict__ W2, const float* __restrict__ fcw) {
    int j = threadIdx.x; // 256 threads
    const float4* r = (const float4*)(W2 + j * OUT_C);
    const float4* f = (const float4*)fcw;
    float s = 0.f;
    #pragma unroll
    for (int o = 0; o < OUT_C / 4; o++) {
        float4 a = r[o], b = f[o];
        s += a.x * b.x + a.y * b.y + a.z * b.z + a.w * b.w;
    }
    g_w[j] = s;
}

// y[n] = dn * sum_{s in N(n)} x'[s]  +  dn^2 * x[n]
// One warp per node. 16 lanes cover a 128-half row (uint4 each); the two
// half-warps process two different neighbors concurrently. HADD2 accumulate,
// flushed to fp32 every 8 pair-steps (16 neighbors per side).
__global__ void k_aggregate(const float* __restrict__ x) {
    int warp = threadIdx.x >> 5, lane = threadIdx.x & 31;
    int n = blockIdx.x * 8 + warp;
    if (n >= N_NODES) return;

    int cl = lane & 15;        // channel group (8 halves)
    int side = lane >> 4;      // which neighbor of the pair

    float fa[8];
    #pragma unroll
    for (int i = 0; i < 8; i++) fa[i] = 0.f;
    __half2 ha[4];
    #pragma unroll
    for (int i = 0; i < 4; i++) ha[i] = __half2half2(__float2half(0.f));

    int beg = g_off[n], end = g_off[n + 1];
    int j = beg;
    for (; j + 32 <= end; j += 32) {
        int s = g_csr[j + lane];
        #pragma unroll
        for (int p = 0; p < 16; p++) {
            int ss = __shfl_sync(0xffffffffu, s, 2 * p + side);
            uint4 raw = g_xh[ss * 16 + cl];
            ha[0] = __hadd2(ha[0], *(const __half2*)&raw.x);
            ha[1] = __hadd2(ha[1], *(const __half2*)&raw.y);
            ha[2] = __hadd2(ha[2], *(const __half2*)&raw.z);
            ha[3] = __hadd2(ha[3], *(const __half2*)&raw.w);
            if (p == 7 || p == 15) {
                #pragma unroll
                for (int i = 0; i < 4; i++) {
                    float2 f = __half22float2(ha[i]);
                    fa[2 * i] += f.x; fa[2 * i + 1] += f.y;
                    ha[i] = __half2half2(__float2half(0.f));
                }
            }
        }
    }
    if (j < end) {
        int idx = j + lane;
        int s = g_csr[(idx < end) ? idx : (end - 1)];   // valid node id in all lanes
        int cnt = end - j;                               // lane-uniform
        int iters = (cnt + 1) >> 1;                      // lane-uniform trip count
        for (int p = 0; p < iters; p++) {
            int nb = 2 * p + side;
            int ss = __shfl_sync(0xffffffffu, s, nb & 31);   // ALL lanes execute
            if (nb < cnt) {
                uint4 raw = g_xh[ss * 16 + cl];
                ha[0] = __hadd2(ha[0], *(const __half2*)&raw.x);
                ha[1] = __hadd2(ha[1], *(const __half2*)&raw.y);
                ha[2] = __hadd2(ha[2], *(const __half2*)&raw.z);
                ha[3] = __hadd2(ha[3], *(const __half2*)&raw.w);
            }
        }
        #pragma unroll
        for (int i = 0; i < 4; i++) {
            float2 f = __half22float2(ha[i]);
            fa[2 * i] += f.x; fa[2 * i + 1] += f.y;
        }
    }

    // combine the two half-warps (same channels, different neighbor subsets)
    #pragma unroll
    for (int i = 0; i < 8; i++) fa[i] += __shfl_xor_sync(0xffffffffu, fa[i], 16);

    // lanes 0-15: scale by dn, add fp32 self term, store
    if (side == 0) {
        float dn = g_dinv[n];
        float sl = dn * dn;
        const float4* xr = (const float4*)(x + n * IN_C + cl * 8);
        float4 x0 = xr[0], x1 = xr[1];
        float4 o0, o1;
        o0.x = dn * fa[0] + sl * x0.x; o0.y = dn * fa[1] + sl * x0.y;
        o0.z = dn * fa[2] + sl * x0.z; o0.w = dn * fa[3] + sl * x0.w;
        o1.x = dn * fa[4] + sl * x1.x; o1.y = dn * fa[5] + sl * x1.y;
        o1.z = dn * fa[6] + sl * x1.z; o1.w = dn * fa[7] + sl * x1.w;
        float4* yr = (float4*)(g_y + n * IN_C + cl * 8);
        yr[0] = o0; yr[1] = o1;
    }
}

// fused: H = y @ W1 + b1 ; s[n] = relu(H[n])·w ; partial[b] = sum_n c[n]*s[n]
// 125 blocks (single wave), 80 nodes per block, warp handles 10 nodes.
__global__ void __launch_bounds__(256) k_gemm_reduce(const float* __restrict__ W1,
                                                     const float* __restrict__ b1) {
    __shared__ float  ys[GR_TILE * IN_C];   // 40 KB
    __shared__ double sred[8];

    int tid = threadIdx.x;
    int m0 = blockIdx.x * GR_TILE;

    {
        const float4* y4 = (const float4*)g_y;
        float4* ys4 = (float4*)ys;
        #pragma unroll
        for (int i = tid; i < GR_TILE * IN_C / 4; i += 256) {
            int m = i >> 5;
            int gm = m0 + m;
            ys4[i] = (gm < N_NODES) ? y4[gm * 32 + (i & 31)]
                                    : make_float4(0.f, 0.f, 0.f, 0.f);
        }
    }
    __syncthreads();

    int jg = tid & 31;   // col group (8 cols of 256)
    int mg = tid >> 5;   // warp id -> 10 nodes
    float acc[10][8];
    #pragma unroll
    for (int a = 0; a < 10; a++)
        #pragma unroll
        for (int b = 0; b < 8; b++) acc[a][b] = 0.f;

    const float*  yb = &ys[mg * 10 * IN_C];
    const float4* w4 = (const float4*)(W1 + jg * 8);

    #pragma unroll 2
    for (int k = 0; k < IN_C; k++) {
        float4 wa = __ldg(&w4[k * (HID_C / 4) + 0]);
        float4 wb = __ldg(&w4[k * (HID_C / 4) + 1]);
        float yv[10];
        #pragma unroll
        for (int i = 0; i < 10; i++) yv[i] = yb[i * IN_C + k];
        #pragma unroll
        for (int i = 0; i < 10; i++) {
            acc[i][0] += yv[i] * wa.x; acc[i][1] += yv[i] * wa.y;
            acc[i][2] += yv[i] * wa.z; acc[i][3] += yv[i] * wa.w;
            acc[i][4] += yv[i] * wb.x; acc[i][5] += yv[i] * wb.y;
            acc[i][6] += yv[i] * wb.z; acc[i][7] += yv[i] * wb.w;
        }
    }

    float bv[8], wv[8];
    *(float4*)&bv[0] = *(const float4*)&b1[jg * 8];
    *(float4*)&bv[4] = *(const float4*)&b1[jg * 8 + 4];
    *(float4*)&wv[0] = *(const float4*)&g_w[jg * 8];
    *(float4*)&wv[4] = *(const float4*)&g_w[jg * 8 + 4];

    double wsum = 0.0;
    #pragma unroll
    for (int mi = 0; mi < 10; mi++) {
        float p = 0.f;
        #pragma unroll
        for (int ji = 0; ji < 8; ji++) {
            float h = acc[mi][ji] + bv[ji];
            h = fmaxf(h, 0.f);
            p += h * wv[ji];
        }
        #pragma unroll
        for (int of = 16; of > 0; of >>= 1) p += __shfl_down_sync(0xffffffffu, p, of);
        if (jg == 0) {
            int n = m0 + mg * 10 + mi;
            if (n < N_NODES) {
                float d = g_dinv[n];
                float cc = g_c[n] + d * d;      // + self-loop column term
                wsum += (double)cc * (double)p;
            }
        }
    }
    if (jg == 0) sred[mg] = wsum;
    __syncthreads();
    if (tid == 0) {
        double s = 0.0;
        #pragma unroll
        for (int i = 0; i < 8; i++) s += sred[i];
        g_part[blockIdx.x] = s;
    }
    // restore the zero-invariant for the next call
    if (tid < GR_TILE) {
        int n = m0 + tid;
        if (n < N_NODES) { g_deg[n] = 0; g_c[n] = 0.f; }
    }
}

__global__ void k_finalize(const float* __restrict__ b2, const float* __restrict__ fcw,
                           const float* __restrict__ fcb, float* __restrict__ out) {
    __shared__ double dsum[128];
    __shared__ float  fsum[128];
    int tid = threadIdx.x; // 128 threads
    double s = 0.0;
    for (int i = tid; i < GR_BLOCKS; i += 128) s += g_part[i];
    dsum[tid] = s;
    fsum[tid] = b2[tid] * fcw[tid];
    __syncthreads();
    for (int of = 64; of > 0; of >>= 1) {
        if (tid < of) { dsum[tid] += dsum[tid + of]; fsum[tid] += fsum[tid + of]; }
        __syncthreads();
    }
    if (tid == 0) {
        out[0] = (float)(dsum[0] / (double)N_NODES) + fsum[0] + fcb[0];
    }
}

// ------------------------------ launcher ------------------------------------
extern "C" void kernel_launch(void* const* d_in, const int* in_sizes, int n_in,
                              void* d_out, int out_size) {
    const float* x    = (const float*)d_in[0];
    const int*   ei   = (const int*)d_in[1];     // edge_index: int32 (JAX x64 disabled)
    const float* W1   = (const float*)d_in[2];
    const float* b1   = (const float*)d_in[3];
    const float* W2   = (const float*)d_in[4];
    const float* b2   = (const float*)d_in[5];
    const float* fcw  = (const float*)d_in[6];
    const float* fcb  = (const float*)d_in[7];
    float* out = (float*)d_out;

    k_count<<<(N_EDGES + 255) / 256, 256>>>(ei);              // idx 0
    k_scan_dinv<<<1, 1024>>>();                               // idx 1
    k_fill_convert<<<(N_EDGES + 255) / 256, 256>>>(ei, x);    // idx 2
    k_aggregate<<<(N_NODES + 7) / 8, 256>>>(x);               // idx 3 (profiled slot)
    k_wvec<<<1, HID_C>>>(W2, fcw);                            // idx 4
    k_gemm_reduce<<<GR_BLOCKS, 256>>>(W1, b1);                // idx 5
    k_finalize<<<1, 128>>>(b2, fcw, fcb, out);                // idx 6
}

// round 13
// speedup vs baseline: 1.1057x; 1.1057x over previous
#include <cuda_runtime.h>
#include <cuda_fp16.h>
#include <math.h>

#define N_NODES 10000
#define N_EDGES 640000
#define IN_C    128
#define HID_C   256
#define OUT_C   128
#define GR_TILE 80
#define GR_BLOCKS ((N_NODES + GR_TILE - 1) / GR_TILE)   // 125

// ------------------------- scratch (device globals) -------------------------
// INVARIANT: g_deg and g_c are all-zero at entry of every kernel_launch call.
__device__ int     g_deg[N_NODES];
__device__ float   g_c[N_NODES];           // column sums of normalized adjacency (edge part)
__device__ int     g_off[N_NODES + 1];
__device__ int     g_cursor[N_NODES];
__device__ int     g_csr[N_EDGES];
__device__ float   g_dinv[N_NODES];
__device__ uint4   g_xh[N_NODES * IN_C / 8];  // dinv-scaled x in fp16, row = 16 uint4
__device__ float   g_y[N_NODES * IN_C];       // (A_hat X)
__device__ float   g_w[HID_C];                // W2 @ fc_w
__device__ double  g_part[GR_BLOCKS];         // per-block partial sums

// ------------------------------- kernels ------------------------------------
__global__ void k_count(const int* __restrict__ ei) {
    int e = blockIdx.x * blockDim.x + threadIdx.x;
    if (e < N_EDGES) {
        int dst = ei[N_EDGES + e];
        if ((unsigned)dst < N_NODES) atomicAdd(&g_deg[dst], 1);
    }
}

// single-block scan, all global traffic coalesced via smem staging
__global__ void __launch_bounds__(1024) k_scan_dinv() {
    __shared__ int sbuf[10240];      // 40 KB staging
    __shared__ int warp_sums[32];
    int t = threadIdx.x;
    int lane = t & 31, wid = t >> 5;

    for (int i = t; i < 10240; i += 1024) sbuf[i] = (i < N_NODES) ? g_deg[i] : 0;
    __syncthreads();

    int base = t * 10;
    int vals[10], tot = 0;
    #pragma unroll
    for (int i = 0; i < 10; i++) { vals[i] = sbuf[base + i]; tot += vals[i]; }

    int incl = tot;
    #pragma unroll
    for (int of = 1; of < 32; of <<= 1) {
        int n = __shfl_up_sync(0xffffffffu, incl, of);
        if (lane >= of) incl += n;
    }
    if (lane == 31) warp_sums[wid] = incl;
    __syncthreads();
    if (wid == 0) {
        int s = warp_sums[lane];
        #pragma unroll
        for (int of = 1; of < 32; of <<= 1) {
            int n = __shfl_up_sync(0xffffffffu, s, of);
            if (lane >= of) s += n;
        }
        warp_sums[lane] = s;
    }
    __syncthreads();
    int excl = ((wid > 0) ? warp_sums[wid - 1] : 0) + incl - tot;

    int run = excl;
    int offv[10];
    #pragma unroll
    for (int i = 0; i < 10; i++) { sbuf[base + i] = run; run += vals[i]; offv[i] = run; }
    __syncthreads();
    for (int i = t; i < N_NODES; i += 1024) g_cursor[i] = sbuf[i];
    __syncthreads();

    #pragma unroll
    for (int i = 0; i < 10; i++) sbuf[base + i] = offv[i];
    __syncthreads();
    if (t == 0) g_off[0] = 0;
    for (int i = t; i < N_NODES; i += 1024) g_off[i + 1] = sbuf[i];
    __syncthreads();

    float* sf = (float*)sbuf;
    #pragma unroll
    for (int i = 0; i < 10; i++) sf[base + i] = rsqrtf((float)(vals[i] + 1)); // +1 self loop
    __syncthreads();
    for (int i = t; i < N_NODES; i += 1024) g_dinv[i] = sf[i];
}

// CSR fill + column sums + convert x -> dinv-scaled fp16 (N_EDGES == N_NODES*IN_C/2)
__global__ void k_fill_convert(const int* __restrict__ ei, const float* __restrict__ x) {
    int e = blockIdx.x * blockDim.x + threadIdx.x;
    if (e < N_EDGES) {
        int src = ei[e];
        int dst = ei[N_EDGES + e];
        if ((unsigned)src < N_NODES && (unsigned)dst < N_NODES) {
            int pos = atomicAdd(&g_cursor[dst], 1);
            g_csr[pos] = src;
            atomicAdd(&g_c[src], g_dinv[src] * g_dinv[dst]);
        }
        // convert one float2 of x, scaled by its row's dinv
        float2 v = ((const float2*)x)[e];
        int row = e >> 6;                       // 64 float2 per row
        float di = g_dinv[row];
        ((__half2*)g_xh)[e] = __floats2half2_rn(di * v.x, di * v.y);
    }
}

// w = W2 @ fc_w  (W2: [256,128] row-major, fc_w: [128])
__global__ void k_wvec(const float* __restrict__ W2, const float* __restrict__ fcw) {
    int j = threadIdx.x; // 256 threads
    const float4* r = (const float4*)(W2 + j * OUT_C);
    const float4* f = (const float4*)fcw;
    float s = 0.f;
    #pragma unroll
    for (int o = 0; o < OUT_C / 4; o++) {
        float4 a = r[o], b = f[o];
        s += a.x * b.x + a.y * b.y + a.z * b.z + a.w * b.w;
    }
    g_w[j] = s;
}

// y[n] = dn * sum_{s in N(n)} x'[s]  +  dn^2 * x[n]
// One warp per node. 16 lanes cover a 128-half row (uint4 each); the two
// half-warps process two different neighbors concurrently. HADD2 accumulate,
// flushed to fp32 every 8 pair-steps (16 neighbors per side).
__global__ void k_aggregate(const float* __restrict__ x) {
    int warp = threadIdx.x >> 5, lane = threadIdx.x & 31;
    int n = blockIdx.x * 8 + warp;
    if (n >= N_NODES) return;

    int cl = lane & 15;        // channel group (8 halves)
    int side = lane >> 4;      // which neighbor of the pair

    float fa[8];
    #pragma unroll
    for (int i = 0; i < 8; i++) fa[i] = 0.f;
    __half2 ha[4];
    #pragma unroll
    for (int i = 0; i < 4; i++) ha[i] = __half2half2(__float2half(0.f));

    int beg = g_off[n], end = g_off[n + 1];
    int j = beg;
    for (; j + 32 <= end; j += 32) {
        int s = g_csr[j + lane];
        #pragma unroll
        for (int p = 0; p < 16; p++) {
            int ss = __shfl_sync(0xffffffffu, s, 2 * p + side);
            uint4 raw = g_xh[ss * 16 + cl];
            ha[0] = __hadd2(ha[0], *(const __half2*)&raw.x);
            ha[1] = __hadd2(ha[1], *(const __half2*)&raw.y);
            ha[2] = __hadd2(ha[2], *(const __half2*)&raw.z);
            ha[3] = __hadd2(ha[3], *(const __half2*)&raw.w);
            if (p == 7 || p == 15) {
                #pragma unroll
                for (int i = 0; i < 4; i++) {
                    float2 f = __half22float2(ha[i]);
                    fa[2 * i] += f.x; fa[2 * i + 1] += f.y;
                    ha[i] = __half2half2(__float2half(0.f));
                }
            }
        }
    }
    if (j < end) {
        int idx = j + lane;
        int s = g_csr[(idx < end) ? idx : (end - 1)];   // valid node id in all lanes
        int cnt = end - j;                               // lane-uniform
        int iters = (cnt + 1) >> 1;                      // lane-uniform trip count
        for (int p = 0; p < iters; p++) {
            int nb = 2 * p + side;
            int ss = __shfl_sync(0xffffffffu, s, nb & 31);   // ALL lanes execute
            if (nb < cnt) {
                uint4 raw = g_xh[ss * 16 + cl];
                ha[0] = __hadd2(ha[0], *(const __half2*)&raw.x);
                ha[1] = __hadd2(ha[1], *(const __half2*)&raw.y);
                ha[2] = __hadd2(ha[2], *(const __half2*)&raw.z);
                ha[3] = __hadd2(ha[3], *(const __half2*)&raw.w);
            }
        }
        #pragma unroll
        for (int i = 0; i < 4; i++) {
            float2 f = __half22float2(ha[i]);
            fa[2 * i] += f.x; fa[2 * i + 1] += f.y;
        }
    }

    // combine the two half-warps (same channels, different neighbor subsets)
    #pragma unroll
    for (int i = 0; i < 8; i++) fa[i] += __shfl_xor_sync(0xffffffffu, fa[i], 16);

    // lanes 0-15: scale by dn, add fp32 self term, store
    if (side == 0) {
        float dn = g_dinv[n];
        float sl = dn * dn;
        const float4* xr = (const float4*)(x + n * IN_C + cl * 8);
        float4 x0 = xr[0], x1 = xr[1];
        float4 o0, o1;
        o0.x = dn * fa[0] + sl * x0.x; o0.y = dn * fa[1] + sl * x0.y;
        o0.z = dn * fa[2] + sl * x0.z; o0.w = dn * fa[3] + sl * x0.w;
        o1.x = dn * fa[4] + sl * x1.x; o1.y = dn * fa[5] + sl * x1.y;
        o1.z = dn * fa[6] + sl * x1.z; o1.w = dn * fa[7] + sl * x1.w;
        float4* yr = (float4*)(g_y + n * IN_C + cl * 8);
        yr[0] = o0; yr[1] = o1;
    }
}

// fused: H = y @ W1 + b1 ; s[n] = relu(H[n])·w ; partial[b] = sum_n c[n]*s[n]
// 125 blocks (single wave), 80 nodes per block, warp handles 10 nodes.
__global__ void __launch_bounds__(256) k_gemm_reduce(const float* __restrict__ W1,
                                                     const float* __restrict__ b1) {
    __shared__ float  ys[GR_TILE * IN_C];   // 40 KB
    __shared__ double sred[8];

    int tid = threadIdx.x;
    int m0 = blockIdx.x * GR_TILE;

    {
        const float4* y4 = (const float4*)g_y;
        float4* ys4 = (float4*)ys;
        #pragma unroll
        for (int i = tid; i < GR_TILE * IN_C / 4; i += 256) {
            int m = i >> 5;
            int gm = m0 + m;
            ys4[i] = (gm < N_NODES) ? y4[gm * 32 + (i & 31)]
                                    : make_float4(0.f, 0.f, 0.f, 0.f);
        }
    }
    __syncthreads();

    int jg = tid & 31;   // col group (8 cols of 256)
    int mg = tid >> 5;   // warp id -> 10 nodes
    float acc[10][8];
    #pragma unroll
    for (int a = 0; a < 10; a++)
        #pragma unroll
        for (int b = 0; b < 8; b++) acc[a][b] = 0.f;

    const float*  yb = &ys[mg * 10 * IN_C];
    const float4* w4 = (const float4*)(W1 + jg * 8);

    #pragma unroll 2
    for (int k = 0; k < IN_C; k++) {
        float4 wa = __ldg(&w4[k * (HID_C / 4) + 0]);
        float4 wb = __ldg(&w4[k * (HID_C / 4) + 1]);
        float yv[10];
        #pragma unroll
        for (int i = 0; i < 10; i++) yv[i] = yb[i * IN_C + k];
        #pragma unroll
        for (int i = 0; i < 10; i++) {
            acc[i][0] += yv[i] * wa.x; acc[i][1] += yv[i] * wa.y;
            acc[i][2] += yv[i] * wa.z; acc[i][3] += yv[i] * wa.w;
            acc[i][4] += yv[i] * wb.x; acc[i][5] += yv[i] * wb.y;
            acc[i][6] += yv[i] * wb.z; acc[i][7] += yv[i] * wb.w;
        }
    }

    float bv[8], wv[8];
    *(float4*)&bv[0] = *(const float4*)&b1[jg * 8];
    *(float4*)&bv[4] = *(const float4*)&b1[jg * 8 + 4];
    *(float4*)&wv[0] = *(const float4*)&g_w[jg * 8];
    *(float4*)&wv[4] = *(const float4*)&g_w[jg * 8 + 4];

    double wsum = 0.0;
    #pragma unroll
    for (int mi = 0; mi < 10; mi++) {
        float p = 0.f;
        #pragma unroll
        for (int ji = 0; ji < 8; ji++) {
            float h = acc[mi][ji] + bv[ji];
            h = fmaxf(h, 0.f);
            p += h * wv[ji];
        }
        #pragma unroll
        for (int of = 16; of > 0; of >>= 1) p += __shfl_down_sync(0xffffffffu, p, of);
        if (jg == 0) {
            int n = m0 + mg * 10 + mi;
            if (n < N_NODES) {
                float d = g_dinv[n];
                float cc = g_c[n] + d * d;      // + self-loop column term
                wsum += (double)cc * (double)p;
            }
        }
    }
    if (jg == 0) sred[mg] = wsum;
    __syncthreads();
    if (tid == 0) {
        double s = 0.0;
        #pragma unroll
        for (int i = 0; i < 8; i++) s += sred[i];
        g_part[blockIdx.x] = s;
    }
    // restore the zero-invariant for the next call
    if (tid < GR_TILE) {
        int n = m0 + tid;
        if (n < N_NODES) { g_deg[n] = 0; g_c[n] = 0.f; }
    }
}

__global__ void k_finalize(const float* __restrict__ b2, const float* __restrict__ fcw,
                           const float* __restrict__ fcb, float* __restrict__ out) {
    __shared__ double dsum[128];
    __shared__ float  fsum[128];
    int tid = threadIdx.x; // 128 threads
    double s = 0.0;
    for (int i = tid; i < GR_BLOCKS; i += 128) s += g_part[i];
    dsum[tid] = s;
    fsum[tid] = b2[tid] * fcw[tid];
    __syncthreads();
    for (int of = 64; of > 0; of >>= 1) {
        if (tid < of) { dsum[tid] += dsum[tid + of]; fsum[tid] += fsum[tid + of]; }
        __syncthreads();
    }
    if (tid == 0) {
        out[0] = (float)(dsum[0] / (double)N_NODES) + fsum[0] + fcb[0];
    }
}

// ------------------------------ launcher ------------------------------------
extern "C" void kernel_launch(void* const* d_in, const int* in_sizes, int n_in,
                              void* d_out, int out_size) {
    const float* x    = (const float*)d_in[0];
    const int*   ei   = (const int*)d_in[1];     // edge_index: int32 (JAX x64 disabled)
    const float* W1   = (const float*)d_in[2];
    const float* b1   = (const float*)d_in[3];
    const float* W2   = (const float*)d_in[4];
    const float* b2   = (const float*)d_in[5];
    const float* fcw  = (const float*)d_in[6];
    const float* fcb  = (const float*)d_in[7];
    float* out = (float*)d_out;

    k_count<<<(N_EDGES + 255) / 256, 256>>>(ei);              // idx 0
    k_scan_dinv<<<1, 1024>>>();                               // idx 1
    k_fill_convert<<<(N_EDGES + 255) / 256, 256>>>(ei, x);    // idx 2
    k_aggregate<<<(N_NODES + 7) / 8, 256>>>(x);               // idx 3 (profiled slot)
    k_wvec<<<1, HID_C>>>(W2, fcw);                            // idx 4
    k_gemm_reduce<<<GR_BLOCKS, 256>>>(W1, b1);                // idx 5
    k_finalize<<<1, 128>>>(b2, fcw, fcb, out);                // idx 6
}